// round 2
// baseline (speedup 1.0000x reference)
#include <cuda_runtime.h>
#include <cuda_bf16.h>
#include <cstdint>

// ===================== problem sizes =====================
#define SEQ   2048
#define HID   8192
#define NTOT  10240          // 8192 q + 1024 k + 1024 v
#define Q_ELEMS   ((size_t)64 * SEQ * 128)
#define KV_ELEMS  ((size_t)8  * SEQ * 128)

// ===================== scratch (bf16 stored as ushort) =====================
__device__ unsigned short g_A_hi[(size_t)SEQ * HID];
__device__ unsigned short g_A_lo[(size_t)SEQ * HID];
__device__ unsigned short g_B_hi[(size_t)NTOT * HID];
__device__ unsigned short g_B_lo[(size_t)NTOT * HID];

// ===================== conversion kernels =====================
__global__ void split_x_kernel(const float* __restrict__ x) {
    size_t n4 = (size_t)SEQ * HID / 4;
    for (size_t i = (size_t)blockIdx.x * blockDim.x + threadIdx.x;
         i < n4; i += (size_t)gridDim.x * blockDim.x) {
        float4 v = reinterpret_cast<const float4*>(x)[i];
        float f[4] = {v.x, v.y, v.z, v.w};
        unsigned short hh[4], ll[4];
        #pragma unroll
        for (int j = 0; j < 4; j++) {
            __nv_bfloat16 hb = __float2bfloat16(f[j]);
            float hf = __bfloat162float(hb);
            __nv_bfloat16 lb = __float2bfloat16(f[j] - hf);
            hh[j] = __bfloat16_as_ushort(hb);
            ll[j] = __bfloat16_as_ushort(lb);
        }
        reinterpret_cast<ushort4*>(g_A_hi)[i] = make_ushort4(hh[0], hh[1], hh[2], hh[3]);
        reinterpret_cast<ushort4*>(g_A_lo)[i] = make_ushort4(ll[0], ll[1], ll[2], ll[3]);
    }
}

// src: [HID rows][ncols] row-major fp32 weight; writes B[n_off+n][k] = src[k][n]
__global__ void transpose_split_kernel(const float* __restrict__ src,
                                       int ncols, int n_off) {
    __shared__ float tile[32][33];
    int c0 = blockIdx.x * 32;     // column (N) base
    int r0 = blockIdx.y * 32;     // row (K) base
    int tx = threadIdx.x, ty = threadIdx.y;
    #pragma unroll
    for (int i = 0; i < 32; i += 8)
        tile[ty + i][tx] = src[(size_t)(r0 + ty + i) * ncols + (c0 + tx)];
    __syncthreads();
    #pragma unroll
    for (int i = 0; i < 32; i += 8) {
        int n = n_off + c0 + ty + i;
        int k = r0 + tx;
        float v = tile[tx][ty + i];
        __nv_bfloat16 hb = __float2bfloat16(v);
        float hf = __bfloat162float(hb);
        __nv_bfloat16 lb = __float2bfloat16(v - hf);
        g_B_hi[(size_t)n * HID + k] = __bfloat16_as_ushort(hb);
        g_B_lo[(size_t)n * HID + k] = __bfloat16_as_ushort(lb);
    }
}

// ===================== GEMM kernel =====================
#define GEMM_THREADS 256
#define STAGES       3
#define STAGE_BYTES  65536       // 4 tiles x 16KB (128 rows x 128B, SW128)
#define GEMM_SMEM    (STAGES * STAGE_BYTES + 1024)

#define LDSM4(r0, r1, r2, r3, addr) \
    asm volatile("ldmatrix.sync.aligned.m8n8.x4.shared.b16 {%0,%1,%2,%3}, [%4];" \
        : "=r"(r0), "=r"(r1), "=r"(r2), "=r"(r3) : "r"(addr))

#define MMA_BF16(d, a, b0, b1) \
    asm volatile("mma.sync.aligned.m16n8k16.row.col.f32.bf16.bf16.f32 " \
        "{%0,%1,%2,%3},{%4,%5,%6,%7},{%8,%9},{%0,%1,%2,%3};" \
        : "+f"((d)[0]), "+f"((d)[1]), "+f"((d)[2]), "+f"((d)[3]) \
        : "r"((a)[0]), "r"((a)[1]), "r"((a)[2]), "r"((a)[3]), "r"(b0), "r"(b1))

__device__ __forceinline__ uint32_t smem_to_u32(const void* p) {
    uint32_t addr;
    asm("{ .reg .u64 t; cvta.to.shared.u64 t, %1; cvt.u32.u64 %0, t; }"
        : "=r"(addr) : "l"(p));
    return addr;
}

// Issue cp.async for one 128-row x 64-bf16-col tile into SW128-swizzled smem.
__device__ __forceinline__ void cp_tile(uint32_t sdst, const unsigned short* gsrc,
                                        int row0, int k0, int tid) {
    const char* g = (const char*)(gsrc + (size_t)row0 * HID + k0);
    #pragma unroll
    for (int i = 0; i < 4; ++i) {
        int idx = i * 256 + tid;            // 0..1023
        int r = idx >> 3;                   // row 0..127
        int c = idx & 7;                    // 16B chunk 0..7
        uint32_t off = (uint32_t)(r * 128 + c * 16);
        off ^= (off >> 3) & 0x70;           // SW128 swizzle
        const char* src = g + (size_t)r * (HID * 2) + c * 16;
        asm volatile("cp.async.cg.shared.global [%0], [%1], 16;"
                     :: "r"(sdst + off), "l"(src) : "memory");
    }
}

__device__ __forceinline__ void load_stage(uint32_t sstage, int m0, int n0,
                                           int k0, int tid) {
    cp_tile(sstage,         g_A_hi, m0, k0, tid);
    cp_tile(sstage + 16384, g_A_lo, m0, k0, tid);
    cp_tile(sstage + 32768, g_B_hi, n0, k0, tid);
    cp_tile(sstage + 49152, g_B_lo, n0, k0, tid);
    asm volatile("cp.async.commit_group;" ::: "memory");
}

__global__ __launch_bounds__(GEMM_THREADS, 1)
void qkv_gemm_kernel(float* __restrict__ out) {
    extern __shared__ char smem_raw[];
    char* sm = (char*)(((uintptr_t)smem_raw + 1023) & ~(uintptr_t)1023);
    uint32_t sbase = smem_to_u32(sm);

    const int tid  = threadIdx.x;
    const int lane = tid & 31;
    const int wid  = tid >> 5;
    const int warp_m = wid & 3;    // 4 warps along M (32 rows each)
    const int warp_n = wid >> 2;   // 2 warps along N (64 cols each)

    const int m0 = (blockIdx.x & 15) << 7;          // M-fastest raster (L2 A reuse)
    const int n0 = (int)(blockIdx.x >> 4) << 7;

    float acc[2][8][4];
    #pragma unroll
    for (int i = 0; i < 2; ++i)
        #pragma unroll
        for (int j = 0; j < 8; ++j)
            #pragma unroll
            for (int r = 0; r < 4; ++r) acc[i][j][r] = 0.f;

    // Precompute per-lane ldmatrix address components.
    // A: lanes 0-15 -> rows 0..15, lanes 16-31 -> same rows, k-chunk +1.
    const int a_row_l = lane & 15;            // row within 16-row frag
    const int a_chi   = lane >> 4;            // 0/1 -> k chunk select
    // B: lanes 0-7 rows j*8.., lanes 8-15 chunk+1, lanes 16-31 rows +8.
    const int b_row_l = (lane & 7) + ((lane >> 4) & 1) * 8;
    const int b_chi   = (lane >> 3) & 1;

    // prologue: prefetch 2 stages
    load_stage(sbase + 0 * STAGE_BYTES, m0, n0, 0, tid);
    load_stage(sbase + 1 * STAGE_BYTES, m0, n0, 64, tid);

    const int NKT = HID / 64;   // 128
    for (int kt = 0; kt < NKT; ++kt) {
        if (kt + 2 < NKT)
            asm volatile("cp.async.wait_group 1;" ::: "memory");
        else
            asm volatile("cp.async.wait_group 0;" ::: "memory");
        __syncthreads();

        if (kt + 2 < NKT)
            load_stage(sbase + ((kt + 2) % STAGES) * STAGE_BYTES,
                       m0, n0, (kt + 2) * 64, tid);

        const uint32_t st = sbase + (kt % STAGES) * STAGE_BYTES;
        const uint32_t sa_hi = st;
        const uint32_t sa_lo = st + 16384;
        const uint32_t sb_hi = st + 32768;
        const uint32_t sb_lo = st + 49152;

        #pragma unroll
        for (int ks = 0; ks < 4; ++ks) {
            // ---- load A fragments (hi, lo) : 2 m-frags each ----
            uint32_t a_hi[2][4], a_lo[2][4];
            #pragma unroll
            for (int mf = 0; mf < 2; ++mf) {
                int row = warp_m * 32 + mf * 16 + a_row_l;
                int c   = 2 * ks + a_chi;
                uint32_t off = (uint32_t)(row * 128 + ((c ^ (row & 7)) * 16));
                LDSM4(a_hi[mf][0], a_hi[mf][1], a_hi[mf][2], a_hi[mf][3], sa_hi + off);
                LDSM4(a_lo[mf][0], a_lo[mf][1], a_lo[mf][2], a_lo[mf][3], sa_lo + off);
            }
            // ---- load B fragments (hi, lo) : 8 n-frags each ----
            uint32_t b_hi[8][2], b_lo[8][2];
            #pragma unroll
            for (int jp = 0; jp < 4; ++jp) {
                int row = warp_n * 64 + jp * 16 + b_row_l;
                int c   = 2 * ks + b_chi;
                uint32_t off = (uint32_t)(row * 128 + ((c ^ (row & 7)) * 16));
                LDSM4(b_hi[2*jp][0], b_hi[2*jp][1], b_hi[2*jp+1][0], b_hi[2*jp+1][1],
                      sb_hi + off);
                LDSM4(b_lo[2*jp][0], b_lo[2*jp][1], b_lo[2*jp+1][0], b_lo[2*jp+1][1],
                      sb_lo + off);
            }
            // ---- 3-product bf16x3 MMAs ----
            #pragma unroll
            for (int mf = 0; mf < 2; ++mf)
                #pragma unroll
                for (int j = 0; j < 8; ++j) {
                    MMA_BF16(acc[mf][j], a_hi[mf], b_hi[j][0], b_hi[j][1]);
                    MMA_BF16(acc[mf][j], a_hi[mf], b_lo[j][0], b_lo[j][1]);
                    MMA_BF16(acc[mf][j], a_lo[mf], b_hi[j][0], b_hi[j][1]);
                }
        }
    }

    // ---- epilogue: scatter accumulators to q/k/v head layout ----
    size_t obase;
    if (n0 < 8192)
        obase = (size_t)(n0 >> 7) * ((size_t)SEQ * 128);
    else if (n0 < 9216)
        obase = Q_ELEMS + (size_t)((n0 - 8192) >> 7) * ((size_t)SEQ * 128);
    else
        obase = Q_ELEMS + KV_ELEMS + (size_t)((n0 - 9216) >> 7) * ((size_t)SEQ * 128);

    const int rbase = m0 + warp_m * 32 + (lane >> 2);
    const int cbase = warp_n * 64 + (lane & 3) * 2;
    #pragma unroll
    for (int mf = 0; mf < 2; ++mf) {
        #pragma unroll
        for (int j = 0; j < 8; ++j) {
            int m = rbase + mf * 16;
            int c = cbase + j * 8;
            float* p0 = out + obase + (size_t)m * 128 + c;
            p0[0] = acc[mf][j][0];
            p0[1] = acc[mf][j][1];
            float* p1 = p0 + 8 * 128;
            p1[0] = acc[mf][j][2];
            p1[1] = acc[mf][j][3];
        }
    }
}

// ===================== host launcher =====================
extern "C" void kernel_launch(void* const* d_in, const int* in_sizes, int n_in,
                              void* d_out, int out_size) {
    const float* x = nullptr; const float* wq = nullptr;
    const float* wk = nullptr; const float* wv = nullptr;
    for (int i = 0; i < n_in; ++i) {
        long long sz = in_sizes[i];
        const float* p = (const float*)d_in[i];
        if (sz == (long long)SEQ * HID)       { if (!x) x = p; }
        else if (sz == (long long)HID * 8192) { if (!wq) wq = p; }
        else if (sz == (long long)HID * 1024) { if (!wk) wk = p; else if (!wv) wv = p; }
    }
    float* out = (float*)d_out;

    cudaFuncSetAttribute(qkv_gemm_kernel,
                         cudaFuncAttributeMaxDynamicSharedMemorySize, GEMM_SMEM);

    // 1) split activations into bf16 hi/lo
    split_x_kernel<<<4096, 256>>>(x);

    // 2) transpose + split weights into B[hi/lo] [NTOT][HID]
    dim3 tb(32, 8);
    transpose_split_kernel<<<dim3(8192 / 32, HID / 32), tb>>>(wq, 8192, 0);
    transpose_split_kernel<<<dim3(1024 / 32, HID / 32), tb>>>(wk, 1024, 8192);
    transpose_split_kernel<<<dim3(1024 / 32, HID / 32), tb>>>(wv, 1024, 9216);

    // 3) bf16x3 mma.sync GEMM + fused q/k/v head scatter
    qkv_gemm_kernel<<<16 * 80, GEMM_THREADS, GEMM_SMEM>>>(out);
}